// round 5
// baseline (speedup 1.0000x reference)
#include <cuda_runtime.h>

#define BATCH 128
#define CIN   9
#define T0    2048
#define T1    1024
#define RR    512
#define NNODES 65536
#define ESING 8192
#define HID   128
#define OUTF  12

// ---------------- scratch ----------------------------------------------------
__device__ __align__(16) float g_tc1[BATCH * 16 * T1];
__device__ __align__(16) float g_nodes[NNODES * 32];
__device__ __align__(16) float g_xa[NNODES * 32];
__device__ __align__(16) float g_h1[NNODES * HID];
__device__ __align__(16) float g_h1a[NNODES * HID];
__device__ float g_meanv[BATCH * HID];

__device__ int   g_ptr[RR + 1];
__device__ int   g_src[ESING + RR];
__device__ float g_wgt[ESING + RR];

// ---------------- fused graph build (1 block) --------------------------------
__global__ void k_graph(const int* __restrict__ ei, int etot) {
    __shared__ int   s_cnt[RR];
    __shared__ int   s_pos[RR];
    __shared__ int   s_ptr[RR + 1];
    __shared__ int   s_scan[RR];
    __shared__ float s_dis[RR];
    int t = threadIdx.x;
    s_cnt[t] = 0;
    s_pos[t] = 0;
    for (int i = t; i < BATCH * HID; i += RR) g_meanv[i] = 0.f;
    __syncthreads();
    for (int e = t; e < ESING; e += RR) atomicAdd(&s_cnt[ei[etot + e]], 1);
    __syncthreads();
    int deg = s_cnt[t] + 1;
    s_dis[t]  = rsqrtf((float)deg);
    s_scan[t] = deg;
    __syncthreads();
    for (int off = 1; off < RR; off <<= 1) {
        int v = (t >= off) ? s_scan[t - off] : 0;
        __syncthreads();
        s_scan[t] += v;
        __syncthreads();
    }
    s_ptr[t + 1] = s_scan[t];
    if (t == 0) s_ptr[0] = 0;
    __syncthreads();
    g_ptr[t + 1] = s_ptr[t + 1];
    if (t == 0) g_ptr[0] = 0;
    for (int e = t; e < ESING; e += RR) {
        int s = ei[e], tt = ei[etot + e];
        int k = atomicAdd(&s_pos[tt], 1);
        int idx = s_ptr[tt] + k;
        g_src[idx] = s;
        g_wgt[idx] = s_dis[s] * s_dis[tt];
    }
    int idx = s_ptr[t] + s_cnt[t];
    g_src[idx] = t;
    g_wgt[idx] = s_dis[t] * s_dis[t];
}

// ---------------- conv1: all 16 ocs per block, one read of x ------------------
__global__ void k_conv1(const float* __restrict__ x, const float* __restrict__ w,
                        const float* __restrict__ bias) {
    __shared__ float sx[CIN][516];
    __shared__ float sw[16][CIN][5];
    __shared__ float sb[16];
    int tid = threadIdx.x;           // 256 threads: og = tid>>7, pos = tid&127
    int og   = tid >> 7;
    int tidp = tid & 127;
    int P0 = blockIdx.x * 256;
    int b  = blockIdx.y;
    int raw0 = 2 * P0 - 2;
    const float* xb = x + (long)b * CIN * T0;
    for (int id = tid; id < CIN * 516; id += 256) {
        int c = id / 516, i = id - c * 516;
        int ti = raw0 + i;
        sx[c][i] = (ti >= 0 && ti < T0) ? xb[c * T0 + ti] : 0.f;
    }
    for (int id = tid; id < 16 * CIN * 5; id += 256)
        ((float*)sw)[id] = w[id];
    if (tid < 16) sb[tid] = bias[tid];
    __syncthreads();

    float r[8][4];
#pragma unroll
    for (int q = 0; q < 8; q++) {
        float bv = sb[og * 8 + q];
#pragma unroll
        for (int j = 0; j < 4; j++) r[q][j] = bv;
    }
#pragma unroll
    for (int c = 0; c < CIN; c++) {
        float v[8];
#pragma unroll
        for (int j = 0; j < 8; j++) v[j] = sx[c][4 * tidp + j];
#pragma unroll
        for (int q = 0; q < 8; q++) {
#pragma unroll
            for (int k = 0; k < 5; k++) {
                float wv = sw[og * 8 + q][c][k];
                r[q][0] = fmaf(v[k],     wv, r[q][0]);
                r[q][1] = fmaf(v[k + 1], wv, r[q][1]);
                r[q][2] = fmaf(v[k + 2], wv, r[q][2]);
                r[q][3] = fmaf(v[k + 3], wv, r[q][3]);
            }
        }
    }
    int p0 = P0 + 2 * tidp;
#pragma unroll
    for (int q = 0; q < 8; q++) {
        int oc = og * 8 + q;
        float o0 = fmaxf(fmaxf(r[q][0], r[q][1]), 0.f);
        float o1 = fmaxf(fmaxf(r[q][2], r[q][3]), 0.f);
        *(float2*)&g_tc1[((long)b * 16 + oc) * T1 + p0] = make_float2(o0, o1);
    }
}

// ---------------- conv2: all 32 ocs per block (512 thr), one read of tc1 ------
__global__ void k_conv2(const float* __restrict__ w, const float* __restrict__ bias) {
    __shared__ float sx[16][516];
    __shared__ float sw[32][16][5];
    __shared__ float sb[32];
    int tid  = threadIdx.x;          // 512 threads: og = tid>>7 (0..3)
    int og   = tid >> 7;
    int tidp = tid & 127;
    int P0 = blockIdx.x * 256;
    int b  = blockIdx.y;
    int raw0 = 2 * P0 - 2;
    const float* hb = g_tc1 + (long)b * 16 * T1;
    for (int id = tid; id < 16 * 516; id += 512) {
        int c = id / 516, i = id - c * 516;
        int ti = raw0 + i;
        sx[c][i] = (ti >= 0 && ti < T1) ? hb[c * T1 + ti] : 0.f;
    }
    for (int id = tid; id < 32 * 16 * 5; id += 512)
        ((float*)sw)[id] = w[id];
    if (tid < 32) sb[tid] = bias[tid];
    __syncthreads();

    float r[8][4];
#pragma unroll
    for (int q = 0; q < 8; q++) {
        float bv = sb[og * 8 + q];
#pragma unroll
        for (int j = 0; j < 4; j++) r[q][j] = bv;
    }
#pragma unroll
    for (int c = 0; c < 16; c++) {
        float v[8];
#pragma unroll
        for (int j = 0; j < 8; j++) v[j] = sx[c][4 * tidp + j];
#pragma unroll
        for (int q = 0; q < 8; q++) {
#pragma unroll
            for (int k = 0; k < 5; k++) {
                float wv = sw[og * 8 + q][c][k];
                r[q][0] = fmaf(v[k],     wv, r[q][0]);
                r[q][1] = fmaf(v[k + 1], wv, r[q][1]);
                r[q][2] = fmaf(v[k + 2], wv, r[q][2]);
                r[q][3] = fmaf(v[k + 3], wv, r[q][3]);
            }
        }
    }
    int p0 = P0 + 2 * tidp;
    long node0 = (long)b * RR + p0;
    float out0[8], out1[8];
#pragma unroll
    for (int q = 0; q < 8; q++) {
        out0[q] = fmaxf(fmaxf(r[q][0], r[q][1]), 0.f);
        out1[q] = fmaxf(fmaxf(r[q][2], r[q][3]), 0.f);
    }
    float4* d0 = (float4*)&g_nodes[node0 * 32 + og * 8];
    float4* d1 = (float4*)&g_nodes[(node0 + 1) * 32 + og * 8];
    d0[0] = make_float4(out0[0], out0[1], out0[2], out0[3]);
    d0[1] = make_float4(out0[4], out0[5], out0[6], out0[7]);
    d1[0] = make_float4(out1[0], out1[1], out1[2], out1[3]);
    d1[1] = make_float4(out1[4], out1[5], out1[6], out1[7]);
}

// ---------------- agg32: one sample per block, L1-resident source -------------
__global__ void k_agg32() {          // grid 128, block 512 (16 warps)
    int b = blockIdx.x;
    const float* __restrict__ inb = g_nodes + (long)b * RR * 32;
    int warp = threadIdx.x >> 5, lane = threadIdx.x & 31;
    for (int t = warp; t < RR; t += 16) {
        int beg = g_ptr[t], end = g_ptr[t + 1];
        float a0 = 0.f, a1 = 0.f;
        int i = beg;
        for (; i + 1 < end; i += 2) {
            a0 = fmaf(g_wgt[i],     __ldg(&inb[g_src[i]     * 32 + lane]), a0);
            a1 = fmaf(g_wgt[i + 1], __ldg(&inb[g_src[i + 1] * 32 + lane]), a1);
        }
        if (i < end) a0 = fmaf(g_wgt[i], __ldg(&inb[g_src[i] * 32 + lane]), a0);
        g_xa[((long)b * RR + t) * 32 + lane] = a0 + a1;
    }
}

// ---------------- agg128: sample x feature-quarter per block ------------------
__global__ void k_agg128() {         // grid (4, 128), block 256 (8 warps)
    int q = blockIdx.x;              // feature quarter
    int b = blockIdx.y;
    const float* __restrict__ inb = g_h1 + (long)b * RR * HID + q * 32;
    int warp = threadIdx.x >> 5, lane = threadIdx.x & 31;
    for (int t = warp; t < RR; t += 8) {
        int beg = g_ptr[t], end = g_ptr[t + 1];
        float a0 = 0.f, a1 = 0.f;
        int i = beg;
        for (; i + 1 < end; i += 2) {
            a0 = fmaf(g_wgt[i],     __ldg(&inb[g_src[i]     * HID + lane]), a0);
            a1 = fmaf(g_wgt[i + 1], __ldg(&inb[g_src[i + 1] * HID + lane]), a1);
        }
        if (i < end) a0 = fmaf(g_wgt[i], __ldg(&inb[g_src[i] * HID + lane]), a0);
        g_h1a[((long)b * RR + t) * HID + q * 32 + lane] = a0 + a1;
    }
}

// ---------------- GEMM1: [N,32]@[32,128] + bias, relu (128-row tiles) ---------
__global__ void k_gemm1(const float* __restrict__ W, const float* __restrict__ bias) {
    __shared__ float as[128][33];
    __shared__ float ws[32][128];
    int tid = threadIdx.x;
    long rowBase = (long)blockIdx.x * 128;
    for (int id = tid; id < 1024; id += 256) {            // 128x32 as float4
        int r = id >> 3, k4 = id & 7;
        float4 v = *(const float4*)(g_xa + (rowBase + r) * 32 + k4 * 4);
        as[r][k4 * 4 + 0] = v.x; as[r][k4 * 4 + 1] = v.y;
        as[r][k4 * 4 + 2] = v.z; as[r][k4 * 4 + 3] = v.w;
    }
    for (int id = tid; id < 1024; id += 256) {            // 32x128 W as float4
        int kk = id >> 5, c4 = id & 31;
        *(float4*)&ws[kk][c4 * 4] = *(const float4*)(W + kk * HID + c4 * 4);
    }
    __syncthreads();
    int rg = tid >> 4, cg = tid & 15, row0 = rg * 8;
    float acc[8][8];
#pragma unroll
    for (int i = 0; i < 8; i++)
#pragma unroll
        for (int j = 0; j < 8; j++) acc[i][j] = 0.f;
#pragma unroll
    for (int k = 0; k < 32; k++) {
        float a[8], bb[8];
#pragma unroll
        for (int i = 0; i < 8; i++) a[i] = as[row0 + i][k];
#pragma unroll
        for (int j = 0; j < 8; j++) bb[j] = ws[k][cg + 16 * j];
#pragma unroll
        for (int i = 0; i < 8; i++)
#pragma unroll
            for (int j = 0; j < 8; j++) acc[i][j] = fmaf(a[i], bb[j], acc[i][j]);
    }
#pragma unroll
    for (int i = 0; i < 8; i++)
#pragma unroll
        for (int j = 0; j < 8; j++) {
            int col = cg + 16 * j;
            g_h1[(rowBase + row0 + i) * HID + col] = fmaxf(acc[i][j] + bias[col], 0.f);
        }
}

// ---------------- GEMM2 + bias + relu + mean ---------------------------------
__global__ void k_gemm2m(const float* __restrict__ W, const float* __restrict__ bias) {
    __shared__ float as[128][33];
    __shared__ float ws[32][128];
    __shared__ float smean[HID];
    int tid = threadIdx.x;
    long rowBase = (long)blockIdx.x * 128;
    int b = blockIdx.x >> 2;
    int rg = tid >> 4, cg = tid & 15, row0 = rg * 8;
    float acc[8][8];
#pragma unroll
    for (int i = 0; i < 8; i++)
#pragma unroll
        for (int j = 0; j < 8; j++) acc[i][j] = 0.f;
    for (int kc = 0; kc < 4; kc++) {
        __syncthreads();
        for (int id = tid; id < 1024; id += 256) {        // 128x32 slice as float4
            int r = id >> 3, k4 = id & 7;
            float4 v = *(const float4*)(g_h1a + (rowBase + r) * HID + kc * 32 + k4 * 4);
            as[r][k4 * 4 + 0] = v.x; as[r][k4 * 4 + 1] = v.y;
            as[r][k4 * 4 + 2] = v.z; as[r][k4 * 4 + 3] = v.w;
        }
        for (int id = tid; id < 1024; id += 256) {        // 32x128 W slice float4
            int kk = id >> 5, c4 = id & 31;
            *(float4*)&ws[kk][c4 * 4] = *(const float4*)(W + (kc * 32 + kk) * HID + c4 * 4);
        }
        __syncthreads();
#pragma unroll
        for (int k = 0; k < 32; k++) {
            float a[8], bb[8];
#pragma unroll
            for (int i = 0; i < 8; i++) a[i] = as[row0 + i][k];
#pragma unroll
            for (int j = 0; j < 8; j++) bb[j] = ws[k][cg + 16 * j];
#pragma unroll
            for (int i = 0; i < 8; i++)
#pragma unroll
                for (int j = 0; j < 8; j++) acc[i][j] = fmaf(a[i], bb[j], acc[i][j]);
        }
    }
    if (tid < HID) smean[tid] = 0.f;
    __syncthreads();
#pragma unroll
    for (int j = 0; j < 8; j++) {
        int col = cg + 16 * j;
        float bv = bias[col];
        float s = 0.f;
#pragma unroll
        for (int i = 0; i < 8; i++) s += fmaxf(acc[i][j] + bv, 0.f);
        atomicAdd(&smean[col], s);
    }
    __syncthreads();
    if (tid < HID) atomicAdd(&g_meanv[b * HID + tid], smean[tid] * (1.0f / RR));
}

// ---------------- fc ---------------------------------------------------------
__global__ void k_fc(const float* __restrict__ fw, const float* __restrict__ fb,
                     float* __restrict__ out) {
    int b = blockIdx.x;
    __shared__ float m[HID];
    m[threadIdx.x] = g_meanv[b * HID + threadIdx.x];
    __syncthreads();
    if (threadIdx.x < OUTF) {
        float acc = fb[threadIdx.x];
#pragma unroll
        for (int f = 0; f < HID; f++)
            acc = fmaf(m[f], fw[f * OUTF + threadIdx.x], acc);
        out[b * OUTF + threadIdx.x] = acc;
    }
}

// ---------------- launch ------------------------------------------------------
extern "C" void kernel_launch(void* const* d_in, const int* in_sizes, int n_in,
                              void* d_out, int out_size) {
    const float* x   = (const float*)d_in[0];
    const int*   ei  = (const int*)  d_in[1];
    const float* c1w = (const float*)d_in[2];
    const float* c1b = (const float*)d_in[3];
    const float* c2w = (const float*)d_in[4];
    const float* c2b = (const float*)d_in[5];
    const float* g1w = (const float*)d_in[6];
    const float* g1b = (const float*)d_in[7];
    const float* g2w = (const float*)d_in[8];
    const float* g2b = (const float*)d_in[9];
    const float* fw  = (const float*)d_in[10];
    const float* fb  = (const float*)d_in[11];
    float* out = (float*)d_out;
    int etot = in_sizes[1] / 2;

    k_graph<<<1, RR>>>(ei, etot);                                // 1
    k_conv1<<<dim3(T1 / 256, BATCH), 256>>>(x, c1w, c1b);        // 2
    k_conv2<<<dim3(RR / 256, BATCH), 512>>>(c2w, c2b);           // 3
    k_agg32<<<BATCH, 512>>>();                                   // 4
    k_gemm1<<<NNODES / 128, 256>>>(g1w, g1b);                    // 5
    k_agg128<<<dim3(4, BATCH), 256>>>();                         // 6 (profiled)
    k_gemm2m<<<NNODES / 128, 256>>>(g2w, g2b);                   // 7
    k_fc<<<BATCH, HID>>>(fw, fb, out);                           // 8
}

// round 6
// speedup vs baseline: 1.0753x; 1.0753x over previous
#include <cuda_runtime.h>

#define BATCH 128
#define CIN   9
#define T0    2048
#define T1    1024
#define RR    512
#define NNODES 65536
#define ESING 8192
#define HID   128
#define OUTF  12

// ---------------- scratch ----------------------------------------------------
__device__ __align__(16) float g_tc1[BATCH * 16 * T1];
__device__ __align__(16) float g_nodes[NNODES * 32];
__device__ __align__(16) float g_xa[NNODES * 32];
__device__ __align__(16) float g_h1[NNODES * HID];
__device__ __align__(16) float g_h1a[NNODES * HID];
__device__ float g_meanv[BATCH * HID];

__device__ int   g_ptr[RR + 1];
__device__ int   g_src[ESING + RR];
__device__ float g_wgt[ESING + RR];

// ---------------- fused graph build (1 block) --------------------------------
__global__ void k_graph(const int* __restrict__ ei, int etot) {
    __shared__ int   s_cnt[RR];
    __shared__ int   s_pos[RR];
    __shared__ int   s_ptr[RR + 1];
    __shared__ int   s_scan[RR];
    __shared__ float s_dis[RR];
    int t = threadIdx.x;
    s_cnt[t] = 0;
    s_pos[t] = 0;
    for (int i = t; i < BATCH * HID; i += RR) g_meanv[i] = 0.f;
    __syncthreads();
    for (int e = t; e < ESING; e += RR) atomicAdd(&s_cnt[ei[etot + e]], 1);
    __syncthreads();
    int deg = s_cnt[t] + 1;
    s_dis[t]  = rsqrtf((float)deg);
    s_scan[t] = deg;
    __syncthreads();
    for (int off = 1; off < RR; off <<= 1) {
        int v = (t >= off) ? s_scan[t - off] : 0;
        __syncthreads();
        s_scan[t] += v;
        __syncthreads();
    }
    s_ptr[t + 1] = s_scan[t];
    if (t == 0) s_ptr[0] = 0;
    __syncthreads();
    g_ptr[t + 1] = s_ptr[t + 1];
    if (t == 0) g_ptr[0] = 0;
    for (int e = t; e < ESING; e += RR) {
        int s = ei[e], tt = ei[etot + e];
        int k = atomicAdd(&s_pos[tt], 1);
        int idx = s_ptr[tt] + k;
        g_src[idx] = s;
        g_wgt[idx] = s_dis[s] * s_dis[tt];
    }
    int idx = s_ptr[t] + s_cnt[t];
    g_src[idx] = t;
    g_wgt[idx] = s_dis[t] * s_dis[t];
}

// ---------------- conv1: all 16 ocs per block, one read of x ------------------
__global__ void k_conv1(const float* __restrict__ x, const float* __restrict__ w,
                        const float* __restrict__ bias) {
    __shared__ float sx[CIN][516];
    __shared__ float sw[16][CIN][5];
    __shared__ float sb[16];
    int tid = threadIdx.x;
    int og   = tid >> 7;
    int tidp = tid & 127;
    int P0 = blockIdx.x * 256;
    int b  = blockIdx.y;
    int raw0 = 2 * P0 - 2;
    const float* xb = x + (long)b * CIN * T0;
    for (int id = tid; id < CIN * 516; id += 256) {
        int c = id / 516, i = id - c * 516;
        int ti = raw0 + i;
        sx[c][i] = (ti >= 0 && ti < T0) ? xb[c * T0 + ti] : 0.f;
    }
    for (int id = tid; id < 16 * CIN * 5; id += 256)
        ((float*)sw)[id] = w[id];
    if (tid < 16) sb[tid] = bias[tid];
    __syncthreads();

    float r[8][4];
#pragma unroll
    for (int q = 0; q < 8; q++) {
        float bv = sb[og * 8 + q];
#pragma unroll
        for (int j = 0; j < 4; j++) r[q][j] = bv;
    }
#pragma unroll
    for (int c = 0; c < CIN; c++) {
        float v[8];
#pragma unroll
        for (int j = 0; j < 8; j++) v[j] = sx[c][4 * tidp + j];
#pragma unroll
        for (int q = 0; q < 8; q++) {
#pragma unroll
            for (int k = 0; k < 5; k++) {
                float wv = sw[og * 8 + q][c][k];
                r[q][0] = fmaf(v[k],     wv, r[q][0]);
                r[q][1] = fmaf(v[k + 1], wv, r[q][1]);
                r[q][2] = fmaf(v[k + 2], wv, r[q][2]);
                r[q][3] = fmaf(v[k + 3], wv, r[q][3]);
            }
        }
    }
    int p0 = P0 + 2 * tidp;
#pragma unroll
    for (int q = 0; q < 8; q++) {
        int oc = og * 8 + q;
        float o0 = fmaxf(fmaxf(r[q][0], r[q][1]), 0.f);
        float o1 = fmaxf(fmaxf(r[q][2], r[q][3]), 0.f);
        *(float2*)&g_tc1[((long)b * 16 + oc) * T1 + p0] = make_float2(o0, o1);
    }
}

// ---------------- conv2: all 32 ocs per block (512 thr), one read of tc1 ------
__global__ void k_conv2(const float* __restrict__ w, const float* __restrict__ bias) {
    __shared__ float sx[16][516];
    __shared__ float sw[32][16][5];
    __shared__ float sb[32];
    int tid  = threadIdx.x;
    int og   = tid >> 7;
    int tidp = tid & 127;
    int P0 = blockIdx.x * 256;
    int b  = blockIdx.y;
    int raw0 = 2 * P0 - 2;
    const float* hb = g_tc1 + (long)b * 16 * T1;
    for (int id = tid; id < 16 * 516; id += 512) {
        int c = id / 516, i = id - c * 516;
        int ti = raw0 + i;
        sx[c][i] = (ti >= 0 && ti < T1) ? hb[c * T1 + ti] : 0.f;
    }
    for (int id = tid; id < 32 * 16 * 5; id += 512)
        ((float*)sw)[id] = w[id];
    if (tid < 32) sb[tid] = bias[tid];
    __syncthreads();

    float r[8][4];
#pragma unroll
    for (int q = 0; q < 8; q++) {
        float bv = sb[og * 8 + q];
#pragma unroll
        for (int j = 0; j < 4; j++) r[q][j] = bv;
    }
#pragma unroll
    for (int c = 0; c < 16; c++) {
        float v[8];
#pragma unroll
        for (int j = 0; j < 8; j++) v[j] = sx[c][4 * tidp + j];
#pragma unroll
        for (int q = 0; q < 8; q++) {
#pragma unroll
            for (int k = 0; k < 5; k++) {
                float wv = sw[og * 8 + q][c][k];
                r[q][0] = fmaf(v[k],     wv, r[q][0]);
                r[q][1] = fmaf(v[k + 1], wv, r[q][1]);
                r[q][2] = fmaf(v[k + 2], wv, r[q][2]);
                r[q][3] = fmaf(v[k + 3], wv, r[q][3]);
            }
        }
    }
    int p0 = P0 + 2 * tidp;
    long node0 = (long)b * RR + p0;
    float out0[8], out1[8];
#pragma unroll
    for (int q = 0; q < 8; q++) {
        out0[q] = fmaxf(fmaxf(r[q][0], r[q][1]), 0.f);
        out1[q] = fmaxf(fmaxf(r[q][2], r[q][3]), 0.f);
    }
    float4* d0 = (float4*)&g_nodes[node0 * 32 + og * 8];
    float4* d1 = (float4*)&g_nodes[(node0 + 1) * 32 + og * 8];
    d0[0] = make_float4(out0[0], out0[1], out0[2], out0[3]);
    d0[1] = make_float4(out0[4], out0[5], out0[6], out0[7]);
    d1[0] = make_float4(out1[0], out1[1], out1[2], out1[3]);
    d1[1] = make_float4(out1[4], out1[5], out1[6], out1[7]);
}

// ---------------- agg32: sample staged in smem, gathers are LDS hits ----------
// grid 128, block 512, 64KB dynamic smem (sx[512][32])
__global__ void k_agg32() {
    extern __shared__ float sx[];              // [RR*32]
    int b = blockIdx.x;
    int tid = threadIdx.x;
    const float4* inb = (const float4*)(g_nodes + (long)b * RR * 32);
    // stage 512x32 floats = 4096 float4, 8 per thread, coalesced
    for (int id = tid; id < RR * 8; id += 512)
        ((float4*)sx)[id] = inb[id];
    __syncthreads();
    int warp = tid >> 5, lane = tid & 31;
    for (int t = warp; t < RR; t += 16) {
        int beg = g_ptr[t], end = g_ptr[t + 1];
        float a0 = 0.f, a1 = 0.f;
        int i = beg;
        for (; i + 1 < end; i += 2) {
            a0 = fmaf(g_wgt[i],     sx[g_src[i]     * 32 + lane], a0);
            a1 = fmaf(g_wgt[i + 1], sx[g_src[i + 1] * 32 + lane], a1);
        }
        if (i < end) a0 = fmaf(g_wgt[i], sx[g_src[i] * 32 + lane], a0);
        g_xa[((long)b * RR + t) * 32 + lane] = a0 + a1;
    }
}

// ---------------- agg128: (quarter, sample) staged in smem --------------------
// grid (4, 128), block 512, 64KB dynamic smem (sx[512][32] = feature quarter)
__global__ void k_agg128() {
    extern __shared__ float sx[];              // [RR*32]
    int q = blockIdx.x;
    int b = blockIdx.y;
    int tid = threadIdx.x;
    const float* src_base = g_h1 + (long)b * RR * HID + q * 32;
    // stage: 512 rows x 32 floats (8 float4 per row), coalesced 128B chunks
    for (int id = tid; id < RR * 8; id += 512) {
        int r = id >> 3, f4 = id & 7;
        ((float4*)sx)[id] = *(const float4*)(src_base + (long)r * HID + f4 * 4);
    }
    __syncthreads();
    int warp = tid >> 5, lane = tid & 31;
    for (int t = warp; t < RR; t += 16) {
        int beg = g_ptr[t], end = g_ptr[t + 1];
        float a0 = 0.f, a1 = 0.f;
        int i = beg;
        for (; i + 1 < end; i += 2) {
            a0 = fmaf(g_wgt[i],     sx[g_src[i]     * 32 + lane], a0);
            a1 = fmaf(g_wgt[i + 1], sx[g_src[i + 1] * 32 + lane], a1);
        }
        if (i < end) a0 = fmaf(g_wgt[i], sx[g_src[i] * 32 + lane], a0);
        g_h1a[((long)b * RR + t) * HID + q * 32 + lane] = a0 + a1;
    }
}

// ---------------- GEMM1: [N,32]@[32,128] + bias, relu (128-row tiles) ---------
__global__ void k_gemm1(const float* __restrict__ W, const float* __restrict__ bias) {
    __shared__ float as[128][33];
    __shared__ float ws[32][128];
    int tid = threadIdx.x;
    long rowBase = (long)blockIdx.x * 128;
    for (int id = tid; id < 1024; id += 256) {
        int r = id >> 3, k4 = id & 7;
        float4 v = *(const float4*)(g_xa + (rowBase + r) * 32 + k4 * 4);
        as[r][k4 * 4 + 0] = v.x; as[r][k4 * 4 + 1] = v.y;
        as[r][k4 * 4 + 2] = v.z; as[r][k4 * 4 + 3] = v.w;
    }
    for (int id = tid; id < 1024; id += 256) {
        int kk = id >> 5, c4 = id & 31;
        *(float4*)&ws[kk][c4 * 4] = *(const float4*)(W + kk * HID + c4 * 4);
    }
    __syncthreads();
    int rg = tid >> 4, cg = tid & 15, row0 = rg * 8;
    float acc[8][8];
#pragma unroll
    for (int i = 0; i < 8; i++)
#pragma unroll
        for (int j = 0; j < 8; j++) acc[i][j] = 0.f;
#pragma unroll
    for (int k = 0; k < 32; k++) {
        float a[8], bb[8];
#pragma unroll
        for (int i = 0; i < 8; i++) a[i] = as[row0 + i][k];
#pragma unroll
        for (int j = 0; j < 8; j++) bb[j] = ws[k][cg + 16 * j];
#pragma unroll
        for (int i = 0; i < 8; i++)
#pragma unroll
            for (int j = 0; j < 8; j++) acc[i][j] = fmaf(a[i], bb[j], acc[i][j]);
    }
#pragma unroll
    for (int i = 0; i < 8; i++)
#pragma unroll
        for (int j = 0; j < 8; j++) {
            int col = cg + 16 * j;
            g_h1[(rowBase + row0 + i) * HID + col] = fmaxf(acc[i][j] + bias[col], 0.f);
        }
}

// ---------------- GEMM2 + bias + relu + mean ---------------------------------
__global__ void k_gemm2m(const float* __restrict__ W, const float* __restrict__ bias) {
    __shared__ float as[128][33];
    __shared__ float ws[32][128];
    __shared__ float smean[HID];
    int tid = threadIdx.x;
    long rowBase = (long)blockIdx.x * 128;
    int b = blockIdx.x >> 2;
    int rg = tid >> 4, cg = tid & 15, row0 = rg * 8;
    float acc[8][8];
#pragma unroll
    for (int i = 0; i < 8; i++)
#pragma unroll
        for (int j = 0; j < 8; j++) acc[i][j] = 0.f;
    for (int kc = 0; kc < 4; kc++) {
        __syncthreads();
        for (int id = tid; id < 1024; id += 256) {
            int r = id >> 3, k4 = id & 7;
            float4 v = *(const float4*)(g_h1a + (rowBase + r) * HID + kc * 32 + k4 * 4);
            as[r][k4 * 4 + 0] = v.x; as[r][k4 * 4 + 1] = v.y;
            as[r][k4 * 4 + 2] = v.z; as[r][k4 * 4 + 3] = v.w;
        }
        for (int id = tid; id < 1024; id += 256) {
            int kk = id >> 5, c4 = id & 31;
            *(float4*)&ws[kk][c4 * 4] = *(const float4*)(W + (kc * 32 + kk) * HID + c4 * 4);
        }
        __syncthreads();
#pragma unroll
        for (int k = 0; k < 32; k++) {
            float a[8], bb[8];
#pragma unroll
            for (int i = 0; i < 8; i++) a[i] = as[row0 + i][k];
#pragma unroll
            for (int j = 0; j < 8; j++) bb[j] = ws[k][cg + 16 * j];
#pragma unroll
            for (int i = 0; i < 8; i++)
#pragma unroll
                for (int j = 0; j < 8; j++) acc[i][j] = fmaf(a[i], bb[j], acc[i][j]);
        }
    }
    if (tid < HID) smean[tid] = 0.f;
    __syncthreads();
#pragma unroll
    for (int j = 0; j < 8; j++) {
        int col = cg + 16 * j;
        float bv = bias[col];
        float s = 0.f;
#pragma unroll
        for (int i = 0; i < 8; i++) s += fmaxf(acc[i][j] + bv, 0.f);
        atomicAdd(&smean[col], s);
    }
    __syncthreads();
    if (tid < HID) atomicAdd(&g_meanv[b * HID + tid], smean[tid] * (1.0f / RR));
}

// ---------------- fc ---------------------------------------------------------
__global__ void k_fc(const float* __restrict__ fw, const float* __restrict__ fb,
                     float* __restrict__ out) {
    int b = blockIdx.x;
    __shared__ float m[HID];
    m[threadIdx.x] = g_meanv[b * HID + threadIdx.x];
    __syncthreads();
    if (threadIdx.x < OUTF) {
        float acc = fb[threadIdx.x];
#pragma unroll
        for (int f = 0; f < HID; f++)
            acc = fmaf(m[f], fw[f * OUTF + threadIdx.x], acc);
        out[b * OUTF + threadIdx.x] = acc;
    }
}

// ---------------- launch ------------------------------------------------------
extern "C" void kernel_launch(void* const* d_in, const int* in_sizes, int n_in,
                              void* d_out, int out_size) {
    const float* x   = (const float*)d_in[0];
    const int*   ei  = (const int*)  d_in[1];
    const float* c1w = (const float*)d_in[2];
    const float* c1b = (const float*)d_in[3];
    const float* c2w = (const float*)d_in[4];
    const float* c2b = (const float*)d_in[5];
    const float* g1w = (const float*)d_in[6];
    const float* g1b = (const float*)d_in[7];
    const float* g2w = (const float*)d_in[8];
    const float* g2b = (const float*)d_in[9];
    const float* fw  = (const float*)d_in[10];
    const float* fb  = (const float*)d_in[11];
    float* out = (float*)d_out;
    int etot = in_sizes[1] / 2;

    const int AGG_SMEM = RR * 32 * (int)sizeof(float);   // 64 KB
    static int attr_done = 0;
    if (!attr_done) {
        cudaFuncSetAttribute(k_agg32,  cudaFuncAttributeMaxDynamicSharedMemorySize, AGG_SMEM);
        cudaFuncSetAttribute(k_agg128, cudaFuncAttributeMaxDynamicSharedMemorySize, AGG_SMEM);
        attr_done = 1;
    }

    k_graph<<<1, RR>>>(ei, etot);                                // 1
    k_conv1<<<dim3(T1 / 256, BATCH), 256>>>(x, c1w, c1b);        // 2
    k_conv2<<<dim3(RR / 256, BATCH), 512>>>(c2w, c2b);           // 3
    k_agg32<<<BATCH, 512, AGG_SMEM>>>();                         // 4
    k_gemm1<<<NNODES / 128, 256>>>(g1w, g1b);                    // 5
    k_agg128<<<dim3(4, BATCH), 512, AGG_SMEM>>>();               // 6 (profiled)
    k_gemm2m<<<NNODES / 128, 256>>>(g2w, g2b);                   // 7
    k_fc<<<BATCH, HID>>>(fw, fb, out);                           // 8
}

// round 10
// speedup vs baseline: 1.1736x; 1.0915x over previous
#include <cuda_runtime.h>

#define BATCH 128
#define CIN   9
#define T0    2048
#define T1    1024
#define RR    512
#define NNODES 65536
#define ESING 8192
#define NEDGE (ESING + RR)      // 8704 incl. self loops
#define HID   128
#define OUTF  12

// ---------------- f32x2 packed-math helpers (sm_103a FFMA2) ------------------
__device__ __forceinline__ unsigned long long pk2(float lo, float hi) {
    unsigned long long r;
    asm("mov.b64 %0, {%1, %2};" : "=l"(r) : "f"(lo), "f"(hi));
    return r;
}
__device__ __forceinline__ void fma2(unsigned long long& d,
                                     unsigned long long a, unsigned long long b) {
    asm("fma.rn.f32x2 %0, %1, %2, %0;" : "+l"(d) : "l"(a), "l"(b));
}
__device__ __forceinline__ float2 upk2(unsigned long long v) {
    float2 f;
    asm("mov.b64 {%0, %1}, %2;" : "=f"(f.x), "=f"(f.y) : "l"(v));
    return f;
}

// ---------------- scratch ----------------------------------------------------
__device__ __align__(16) float g_tc1[BATCH * 16 * T1];
__device__ __align__(16) float g_nodes[NNODES * 32];
__device__ __align__(16) float g_xa[NNODES * 32];
__device__ __align__(16) float g_h1[NNODES * HID];
__device__ __align__(16) float g_h1a[NNODES * HID];
__device__ float g_meanv[BATCH * HID];

__device__ int  g_ptr[RR + 1];
__device__ int2 g_edge[NEDGE];      // {src, weight bits}

// ---------------- fused graph build (1 block) --------------------------------
__global__ void k_graph(const int* __restrict__ ei, int etot) {
    __shared__ int   s_cnt[RR];
    __shared__ int   s_pos[RR];
    __shared__ int   s_ptr[RR + 1];
    __shared__ int   s_scan[RR];
    __shared__ float s_dis[RR];
    int t = threadIdx.x;
    s_cnt[t] = 0;
    s_pos[t] = 0;
    for (int i = t; i < BATCH * HID; i += RR) g_meanv[i] = 0.f;
    __syncthreads();
    for (int e = t; e < ESING; e += RR) atomicAdd(&s_cnt[ei[etot + e]], 1);
    __syncthreads();
    int deg = s_cnt[t] + 1;
    s_dis[t]  = rsqrtf((float)deg);
    s_scan[t] = deg;
    __syncthreads();
    for (int off = 1; off < RR; off <<= 1) {
        int v = (t >= off) ? s_scan[t - off] : 0;
        __syncthreads();
        s_scan[t] += v;
        __syncthreads();
    }
    s_ptr[t + 1] = s_scan[t];
    if (t == 0) s_ptr[0] = 0;
    __syncthreads();
    g_ptr[t + 1] = s_ptr[t + 1];
    if (t == 0) g_ptr[0] = 0;
    for (int e = t; e < ESING; e += RR) {
        int s = ei[e], tt = ei[etot + e];
        int k = atomicAdd(&s_pos[tt], 1);
        int idx = s_ptr[tt] + k;
        g_edge[idx] = make_int2(s, __float_as_int(s_dis[s] * s_dis[tt]));
    }
    int idx = s_ptr[t] + s_cnt[t];
    g_edge[idx] = make_int2(t, __float_as_int(s_dis[t] * s_dis[t]));
}

// ---------------- conv1: all 16 ocs per block, FFMA2 -------------------------
__global__ void k_conv1(const float* __restrict__ x, const float* __restrict__ w,
                        const float* __restrict__ bias) {
    __shared__ float sx[CIN][516];
    __shared__ float sw[16][CIN][5];
    __shared__ float sb[16];
    int tid = threadIdx.x;
    int og   = tid >> 7;
    int tidp = tid & 127;
    int P0 = blockIdx.x * 256;
    int b  = blockIdx.y;
    int raw0 = 2 * P0 - 2;
    const float* xb = x + (long)b * CIN * T0;
    for (int id = tid; id < CIN * 516; id += 256) {
        int c = id / 516, i = id - c * 516;
        int ti = raw0 + i;
        sx[c][i] = (ti >= 0 && ti < T0) ? xb[c * T0 + ti] : 0.f;
    }
    for (int id = tid; id < 16 * CIN * 5; id += 256)
        ((float*)sw)[id] = w[id];
    if (tid < 16) sb[tid] = bias[tid];
    __syncthreads();

    unsigned long long r01[8], r23[8];
#pragma unroll
    for (int q = 0; q < 8; q++) {
        float bv = sb[og * 8 + q];
        r01[q] = pk2(bv, bv);
        r23[q] = pk2(bv, bv);
    }
#pragma unroll
    for (int c = 0; c < CIN; c++) {
        float v[8];
#pragma unroll
        for (int j = 0; j < 8; j++) v[j] = sx[c][4 * tidp + j];
        unsigned long long pa[7];
#pragma unroll
        for (int j = 0; j < 7; j++) pa[j] = pk2(v[j], v[j + 1]);
#pragma unroll
        for (int q = 0; q < 8; q++) {
#pragma unroll
            for (int k = 0; k < 5; k++) {
                float wv = sw[og * 8 + q][c][k];
                unsigned long long wq = pk2(wv, wv);
                fma2(r01[q], pa[k], wq);
                fma2(r23[q], pa[k + 2], wq);
            }
        }
    }
    int p0 = P0 + 2 * tidp;
#pragma unroll
    for (int q = 0; q < 8; q++) {
        int oc = og * 8 + q;
        float2 f01 = upk2(r01[q]), f23 = upk2(r23[q]);
        float o0 = fmaxf(fmaxf(f01.x, f01.y), 0.f);
        float o1 = fmaxf(fmaxf(f23.x, f23.y), 0.f);
        *(float2*)&g_tc1[((long)b * 16 + oc) * T1 + p0] = make_float2(o0, o1);
    }
}

// ---------------- conv2: all 32 ocs per block (512 thr), FFMA2 ---------------
__global__ void k_conv2(const float* __restrict__ w, const float* __restrict__ bias) {
    __shared__ float sx[16][516];
    __shared__ float sw[32][16][5];
    __shared__ float sb[32];
    int tid  = threadIdx.x;
    int og   = tid >> 7;
    int tidp = tid & 127;
    int P0 = blockIdx.x * 256;
    int b  = blockIdx.y;
    int raw0 = 2 * P0 - 2;
    const float* hb = g_tc1 + (long)b * 16 * T1;
    for (int id = tid; id < 16 * 516; id += 512) {
        int c = id / 516, i = id - c * 516;
        int ti = raw0 + i;
        sx[c][i] = (ti >= 0 && ti < T1) ? hb[c * T1 + ti] : 0.f;
    }
    for (int id = tid; id < 32 * 16 * 5; id += 512)
        ((float*)sw)[id] = w[id];
    if (tid < 32) sb[tid] = bias[tid];
    __syncthreads();

    unsigned long long r01[8], r23[8];
#pragma unroll
    for (int q = 0; q < 8; q++) {
        float bv = sb[og * 8 + q];
        r01[q] = pk2(bv, bv);
        r23[q] = pk2(bv, bv);
    }
#pragma unroll
    for (int c = 0; c < 16; c++) {
        float v[8];
#pragma unroll
        for (int j = 0; j < 8; j++) v[j] = sx[c][4 * tidp + j];
        unsigned long long pa[7];
#pragma unroll
        for (int j = 0; j < 7; j++) pa[j] = pk2(v[j], v[j + 1]);
#pragma unroll
        for (int q = 0; q < 8; q++) {
#pragma unroll
            for (int k = 0; k < 5; k++) {
                float wv = sw[og * 8 + q][c][k];
                unsigned long long wq = pk2(wv, wv);
                fma2(r01[q], pa[k], wq);
                fma2(r23[q], pa[k + 2], wq);
            }
        }
    }
    int p0 = P0 + 2 * tidp;
    long node0 = (long)b * RR + p0;
    float out0[8], out1[8];
#pragma unroll
    for (int q = 0; q < 8; q++) {
        float2 f01 = upk2(r01[q]), f23 = upk2(r23[q]);
        out0[q] = fmaxf(fmaxf(f01.x, f01.y), 0.f);
        out1[q] = fmaxf(fmaxf(f23.x, f23.y), 0.f);
    }
    float4* d0 = (float4*)&g_nodes[node0 * 32 + og * 8];
    float4* d1 = (float4*)&g_nodes[(node0 + 1) * 32 + og * 8];
    d0[0] = make_float4(out0[0], out0[1], out0[2], out0[3]);
    d0[1] = make_float4(out0[4], out0[5], out0[6], out0[7]);
    d1[0] = make_float4(out1[0], out1[1], out1[2], out1[3]);
    d1[1] = make_float4(out1[4], out1[5], out1[6], out1[7]);
}

// ---------------- agg smem layout: data[RR*32] | edges[NEDGE] | ptr[RR+1] ----
#define AGG_SMEM_BYTES (RR * 32 * 4 + NEDGE * 8 + (RR + 1) * 4)

// ---------------- agg32: data + edges + ptr all in smem ----------------------
__global__ void k_agg32() {
    extern __shared__ char smemraw[];
    float* sx  = (float*)smemraw;
    int2*  se  = (int2*)(smemraw + RR * 32 * 4);
    int*  sptr = (int*)(smemraw + RR * 32 * 4 + NEDGE * 8);
    int b = blockIdx.x;
    int tid = threadIdx.x;
    const float4* inb = (const float4*)(g_nodes + (long)b * RR * 32);
    for (int id = tid; id < RR * 8; id += 512)
        ((float4*)sx)[id] = inb[id];
    for (int id = tid; id < NEDGE; id += 512)
        se[id] = g_edge[id];
    for (int id = tid; id <= RR; id += 512)
        sptr[id] = g_ptr[id];
    __syncthreads();
    int warp = tid >> 5, lane = tid & 31;
    for (int t = warp; t < RR; t += 16) {
        int beg = sptr[t], end = sptr[t + 1];
        float a0 = 0.f, a1 = 0.f;
        int i = beg;
        for (; i + 1 < end; i += 2) {
            int2 e0 = se[i], e1 = se[i + 1];
            a0 = fmaf(__int_as_float(e0.y), sx[e0.x * 32 + lane], a0);
            a1 = fmaf(__int_as_float(e1.y), sx[e1.x * 32 + lane], a1);
        }
        if (i < end) {
            int2 e0 = se[i];
            a0 = fmaf(__int_as_float(e0.y), sx[e0.x * 32 + lane], a0);
        }
        g_xa[((long)b * RR + t) * 32 + lane] = a0 + a1;
    }
}

// ---------------- agg128: (quarter, sample); same smem scheme ----------------
__global__ void k_agg128() {
    extern __shared__ char smemraw[];
    float* sx  = (float*)smemraw;
    int2*  se  = (int2*)(smemraw + RR * 32 * 4);
    int*  sptr = (int*)(smemraw + RR * 32 * 4 + NEDGE * 8);
    int q = blockIdx.x;
    int b = blockIdx.y;
    int tid = threadIdx.x;
    const float* src_base = g_h1 + (long)b * RR * HID + q * 32;
    for (int id = tid; id < RR * 8; id += 512) {
        int r = id >> 3, f4 = id & 7;
        ((float4*)sx)[id] = *(const float4*)(src_base + (long)r * HID + f4 * 4);
    }
    for (int id = tid; id < NEDGE; id += 512)
        se[id] = g_edge[id];
    for (int id = tid; id <= RR; id += 512)
        sptr[id] = g_ptr[id];
    __syncthreads();
    int warp = tid >> 5, lane = tid & 31;
    for (int t = warp; t < RR; t += 16) {
        int beg = sptr[t], end = sptr[t + 1];
        float a0 = 0.f, a1 = 0.f;
        int i = beg;
        for (; i + 1 < end; i += 2) {
            int2 e0 = se[i], e1 = se[i + 1];
            a0 = fmaf(__int_as_float(e0.y), sx[e0.x * 32 + lane], a0);
            a1 = fmaf(__int_as_float(e1.y), sx[e1.x * 32 + lane], a1);
        }
        if (i < end) {
            int2 e0 = se[i];
            a0 = fmaf(__int_as_float(e0.y), sx[e0.x * 32 + lane], a0);
        }
        g_h1a[((long)b * RR + t) * HID + q * 32 + lane] = a0 + a1;
    }
}

// ---------------- GEMM1: [N,32]@[32,128] + bias, relu, FFMA2 -----------------
__global__ void k_gemm1(const float* __restrict__ W, const float* __restrict__ bias) {
    __shared__ float as[128][33];
    __shared__ float ws[32][128];
    int tid = threadIdx.x;
    long rowBase = (long)blockIdx.x * 128;
    for (int id = tid; id < 1024; id += 256) {
        int r = id >> 3, k4 = id & 7;
        float4 v = *(const float4*)(g_xa + (rowBase + r) * 32 + k4 * 4);
        as[r][k4 * 4 + 0] = v.x; as[r][k4 * 4 + 1] = v.y;
        as[r][k4 * 4 + 2] = v.z; as[r][k4 * 4 + 3] = v.w;
    }
    for (int id = tid; id < 1024; id += 256) {
        int kk = id >> 5, c4 = id & 31;
        *(float4*)&ws[kk][c4 * 4] = *(const float4*)(W + kk * HID + c4 * 4);
    }
    __syncthreads();
    int rg = tid >> 4, cg = tid & 15, row0 = rg * 8;
    unsigned long long acc2[8][4];
#pragma unroll
    for (int i = 0; i < 8; i++)
#pragma unroll
        for (int m = 0; m < 4; m++) acc2[i][m] = 0ULL;
#pragma unroll
    for (int k = 0; k < 32; k++) {
        unsigned long long ap[8], bp[4];
#pragma unroll
        for (int i = 0; i < 8; i++) {
            float a = as[row0 + i][k];
            ap[i] = pk2(a, a);
        }
#pragma unroll
        for (int m = 0; m < 4; m++)
            bp[m] = pk2(ws[k][cg + 32 * m], ws[k][cg + 16 + 32 * m]);
#pragma unroll
        for (int i = 0; i < 8; i++)
#pragma unroll
            for (int m = 0; m < 4; m++) fma2(acc2[i][m], ap[i], bp[m]);
    }
#pragma unroll
    for (int i = 0; i < 8; i++)
#pragma unroll
        for (int m = 0; m < 4; m++) {
            float2 f = upk2(acc2[i][m]);
            int c0 = cg + 32 * m, c1 = cg + 16 + 32 * m;
            g_h1[(rowBase + row0 + i) * HID + c0] = fmaxf(f.x + bias[c0], 0.f);
            g_h1[(rowBase + row0 + i) * HID + c1] = fmaxf(f.y + bias[c1], 0.f);
        }
}

// ---------------- GEMM2 + bias + relu + mean, FFMA2 --------------------------
__global__ void k_gemm2m(const float* __restrict__ W, const float* __restrict__ bias) {
    __shared__ float as[128][33];
    __shared__ float ws[32][128];
    __shared__ float smean[HID];
    int tid = threadIdx.x;
    long rowBase = (long)blockIdx.x * 128;
    int b = blockIdx.x >> 2;
    int rg = tid >> 4, cg = tid & 15, row0 = rg * 8;
    unsigned long long acc2[8][4];
#pragma unroll
    for (int i = 0; i < 8; i++)
#pragma unroll
        for (int m = 0; m < 4; m++) acc2[i][m] = 0ULL;
    for (int kc = 0; kc < 4; kc++) {
        __syncthreads();
        for (int id = tid; id < 1024; id += 256) {
            int r = id >> 3, k4 = id & 7;
            float4 v = *(const float4*)(g_h1a + (rowBase + r) * HID + kc * 32 + k4 * 4);
            as[r][k4 * 4 + 0] = v.x; as[r][k4 * 4 + 1] = v.y;
            as[r][k4 * 4 + 2] = v.z; as[r][k4 * 4 + 3] = v.w;
        }
        for (int id = tid; id < 1024; id += 256) {
            int kk = id >> 5, c4 = id & 31;
            *(float4*)&ws[kk][c4 * 4] = *(const float4*)(W + (kc * 32 + kk) * HID + c4 * 4);
        }
        __syncthreads();
#pragma unroll
        for (int k = 0; k < 32; k++) {
            unsigned long long ap[8], bp[4];
#pragma unroll
            for (int i = 0; i < 8; i++) {
                float a = as[row0 + i][k];
                ap[i] = pk2(a, a);
            }
#pragma unroll
            for (int m = 0; m < 4; m++)
                bp[m] = pk2(ws[k][cg + 32 * m], ws[k][cg + 16 + 32 * m]);
#pragma unroll
            for (int i = 0; i < 8; i++)
#pragma unroll
                for (int m = 0; m < 4; m++) fma2(acc2[i][m], ap[i], bp[m]);
        }
    }
    if (tid < HID) smean[tid] = 0.f;
    __syncthreads();
#pragma unroll
    for (int m = 0; m < 4; m++) {
        int c0 = cg + 32 * m, c1 = cg + 16 + 32 * m;
        float b0 = bias[c0], b1 = bias[c1];
        float s0 = 0.f, s1 = 0.f;
#pragma unroll
        for (int i = 0; i < 8; i++) {
            float2 f = upk2(acc2[i][m]);
            s0 += fmaxf(f.x + b0, 0.f);
            s1 += fmaxf(f.y + b1, 0.f);
        }
        atomicAdd(&smean[c0], s0);
        atomicAdd(&smean[c1], s1);
    }
    __syncthreads();
    if (tid < HID) atomicAdd(&g_meanv[b * HID + tid], smean[tid] * (1.0f / RR));
}

// ---------------- fc ---------------------------------------------------------
__global__ void k_fc(const float* __restrict__ fw, const float* __restrict__ fb,
                     float* __restrict__ out) {
    int b = blockIdx.x;
    __shared__ float m[HID];
    m[threadIdx.x] = g_meanv[b * HID + threadIdx.x];
    __syncthreads();
    if (threadIdx.x < OUTF) {
        float acc = fb[threadIdx.x];
#pragma unroll
        for (int f = 0; f < HID; f++)
            acc = fmaf(m[f], fw[f * OUTF + threadIdx.x], acc);
        out[b * OUTF + threadIdx.x] = acc;
    }
}

// ---------------- launch ------------------------------------------------------
extern "C" void kernel_launch(void* const* d_in, const int* in_sizes, int n_in,
                              void* d_out, int out_size) {
    const float* x   = (const float*)d_in[0];
    const int*   ei  = (const int*)  d_in[1];
    const float* c1w = (const float*)d_in[2];
    const float* c1b = (const float*)d_in[3];
    const float* c2w = (const float*)d_in[4];
    const float* c2b = (const float*)d_in[5];
    const float* g1w = (const float*)d_in[6];
    const float* g1b = (const float*)d_in[7];
    const float* g2w = (const float*)d_in[8];
    const float* g2b = (const float*)d_in[9];
    const float* fw  = (const float*)d_in[10];
    const float* fb  = (const float*)d_in[11];
    float* out = (float*)d_out;
    int etot = in_sizes[1] / 2;

    static int attr_done = 0;
    if (!attr_done) {
        cudaFuncSetAttribute(k_agg32,  cudaFuncAttributeMaxDynamicSharedMemorySize, AGG_SMEM_BYTES);
        cudaFuncSetAttribute(k_agg128, cudaFuncAttributeMaxDynamicSharedMemorySize, AGG_SMEM_BYTES);
        attr_done = 1;
    }

    k_graph<<<1, RR>>>(ei, etot);                                // 1
    k_conv1<<<dim3(T1 / 256, BATCH), 256>>>(x, c1w, c1b);        // 2
    k_conv2<<<dim3(RR / 256, BATCH), 512>>>(c2w, c2b);           // 3
    k_agg32<<<BATCH, 512, AGG_SMEM_BYTES>>>();                   // 4
    k_gemm1<<<NNODES / 128, 256>>>(g1w, g1b);                    // 5
    k_agg128<<<dim3(4, BATCH), 512, AGG_SMEM_BYTES>>>();         // 6 (profiled)
    k_gemm2m<<<NNODES / 128, 256>>>(g2w, g2b);                   // 7
    k_fc<<<BATCH, HID>>>(fw, fb, out);                           // 8
}

// round 12
// speedup vs baseline: 1.1878x; 1.0121x over previous
#include <cuda_runtime.h>

#define BATCH 128
#define CIN   9
#define T0    2048
#define T1    1024
#define RR    512
#define NNODES 65536
#define ESING 8192
#define NEDGE (ESING + RR)      // 8704 incl. self loops
#define HID   128
#define OUTF  12

// ---------------- f32x2 packed-math helpers (sm_103a FFMA2) ------------------
__device__ __forceinline__ unsigned long long pk2(float lo, float hi) {
    unsigned long long r;
    asm("mov.b64 %0, {%1, %2};" : "=l"(r) : "f"(lo), "f"(hi));
    return r;
}
__device__ __forceinline__ void fma2(unsigned long long& d,
                                     unsigned long long a, unsigned long long b) {
    asm("fma.rn.f32x2 %0, %1, %2, %0;" : "+l"(d) : "l"(a), "l"(b));
}
__device__ __forceinline__ float2 upk2(unsigned long long v) {
    float2 f;
    asm("mov.b64 {%0, %1}, %2;" : "=f"(f.x), "=f"(f.y) : "l"(v));
    return f;
}

// ---------------- scratch ----------------------------------------------------
__device__ __align__(16) float g_tc1[BATCH * 16 * T1];
__device__ __align__(16) float g_nodes[NNODES * 32];
__device__ __align__(16) float g_xa[NNODES * 32];
__device__ __align__(16) float g_h1[NNODES * HID];
__device__ __align__(16) float g_h1a[NNODES * HID];
__device__ float g_meanv[BATCH * HID];

__device__ int   g_cnt[RR];
__device__ int   g_pos[RR];
__device__ float g_dis[RR];
__device__ int   g_ptr[RR + 1];
__device__ int2  g_edge[NEDGE];     // {src*32, weight bits}

// ---------------- graph build: zero / count / scan+self / fill ---------------
__global__ void k_zero() {          // 1 block, 512 thr
    int t = threadIdx.x;
    g_cnt[t] = 0;
    g_pos[t] = 0;
    for (int i = t; i < BATCH * HID; i += RR) g_meanv[i] = 0.f;
}

__global__ void k_count(const int* __restrict__ ei, int etot) {  // 32 x 256
    int e = blockIdx.x * 256 + threadIdx.x;
    atomicAdd(&g_cnt[__ldg(&ei[etot + e])], 1);
}

__global__ void k_scan() {          // 1 block, 512 thr; shfl scan + self loops
    __shared__ int wsum[16];
    int t = threadIdx.x;
    int lane = t & 31, w = t >> 5;
    int deg = g_cnt[t] + 1;
    float dis = rsqrtf((float)deg);
    g_dis[t] = dis;
    int v = deg;
#pragma unroll
    for (int off = 1; off < 32; off <<= 1) {
        int n = __shfl_up_sync(0xffffffffu, v, off);
        if (lane >= off) v += n;
    }
    if (lane == 31) wsum[w] = v;
    __syncthreads();
    if (w == 0) {
        int s = (lane < 16) ? wsum[lane] : 0;
#pragma unroll
        for (int off = 1; off < 16; off <<= 1) {
            int n = __shfl_up_sync(0xffffffffu, s, off);
            if (lane >= off) s += n;
        }
        if (lane < 16) wsum[lane] = s;
    }
    __syncthreads();
    int incl = v + ((w > 0) ? wsum[w - 1] : 0);
    g_ptr[t + 1] = incl;
    if (t == 0) g_ptr[0] = 0;
    // self-loop occupies the LAST slot of node t's range: ptr[t]+cnt[t] = incl-1
    g_edge[incl - 1] = make_int2(t * 32, __float_as_int(dis * dis));
}

__global__ void k_fill(const int* __restrict__ ei, int etot) {   // 32 x 256
    int e = blockIdx.x * 256 + threadIdx.x;
    int s = __ldg(&ei[e]);
    int t = __ldg(&ei[etot + e]);
    int k = atomicAdd(&g_pos[t], 1);
    g_edge[__ldg(&g_ptr[t]) + k] =
        make_int2(s * 32, __float_as_int(g_dis[s] * g_dis[t]));
}

// ---------------- conv1: all 16 ocs per block, FFMA2 -------------------------
__global__ void k_conv1(const float* __restrict__ x, const float* __restrict__ w,
                        const float* __restrict__ bias) {
    __shared__ float sx[CIN][516];
    __shared__ float sw[16][CIN][5];
    __shared__ float sb[16];
    int tid = threadIdx.x;
    int og   = tid >> 7;
    int tidp = tid & 127;
    int P0 = blockIdx.x * 256;
    int b  = blockIdx.y;
    int raw0 = 2 * P0 - 2;
    const float* xb = x + (long)b * CIN * T0;
    for (int id = tid; id < CIN * 516; id += 256) {
        int c = id / 516, i = id - c * 516;
        int ti = raw0 + i;
        sx[c][i] = (ti >= 0 && ti < T0) ? xb[c * T0 + ti] : 0.f;
    }
    for (int id = tid; id < 16 * CIN * 5; id += 256)
        ((float*)sw)[id] = w[id];
    if (tid < 16) sb[tid] = bias[tid];
    __syncthreads();

    unsigned long long r01[8], r23[8];
#pragma unroll
    for (int q = 0; q < 8; q++) {
        float bv = sb[og * 8 + q];
        r01[q] = pk2(bv, bv);
        r23[q] = pk2(bv, bv);
    }
#pragma unroll
    for (int c = 0; c < CIN; c++) {
        float v[8];
#pragma unroll
        for (int j = 0; j < 8; j++) v[j] = sx[c][4 * tidp + j];
        unsigned long long pa[7];
#pragma unroll
        for (int j = 0; j < 7; j++) pa[j] = pk2(v[j], v[j + 1]);
#pragma unroll
        for (int q = 0; q < 8; q++) {
#pragma unroll
            for (int k = 0; k < 5; k++) {
                float wv = sw[og * 8 + q][c][k];
                unsigned long long wq = pk2(wv, wv);
                fma2(r01[q], pa[k], wq);
                fma2(r23[q], pa[k + 2], wq);
            }
        }
    }
    int p0 = P0 + 2 * tidp;
#pragma unroll
    for (int q = 0; q < 8; q++) {
        int oc = og * 8 + q;
        float2 f01 = upk2(r01[q]), f23 = upk2(r23[q]);
        float o0 = fmaxf(fmaxf(f01.x, f01.y), 0.f);
        float o1 = fmaxf(fmaxf(f23.x, f23.y), 0.f);
        *(float2*)&g_tc1[((long)b * 16 + oc) * T1 + p0] = make_float2(o0, o1);
    }
}

// ---------------- conv2: all 32 ocs per block (512 thr), FFMA2 ---------------
__global__ void k_conv2(const float* __restrict__ w, const float* __restrict__ bias) {
    __shared__ float sx[16][516];
    __shared__ float sw[32][16][5];
    __shared__ float sb[32];
    int tid  = threadIdx.x;
    int og   = tid >> 7;
    int tidp = tid & 127;
    int P0 = blockIdx.x * 256;
    int b  = blockIdx.y;
    int raw0 = 2 * P0 - 2;
    const float* hb = g_tc1 + (long)b * 16 * T1;
    for (int id = tid; id < 16 * 516; id += 512) {
        int c = id / 516, i = id - c * 516;
        int ti = raw0 + i;
        sx[c][i] = (ti >= 0 && ti < T1) ? hb[c * T1 + ti] : 0.f;
    }
    for (int id = tid; id < 32 * 16 * 5; id += 512)
        ((float*)sw)[id] = w[id];
    if (tid < 32) sb[tid] = bias[tid];
    __syncthreads();

    unsigned long long r01[8], r23[8];
#pragma unroll
    for (int q = 0; q < 8; q++) {
        float bv = sb[og * 8 + q];
        r01[q] = pk2(bv, bv);
        r23[q] = pk2(bv, bv);
    }
#pragma unroll
    for (int c = 0; c < 16; c++) {
        float v[8];
#pragma unroll
        for (int j = 0; j < 8; j++) v[j] = sx[c][4 * tidp + j];
        unsigned long long pa[7];
#pragma unroll
        for (int j = 0; j < 7; j++) pa[j] = pk2(v[j], v[j + 1]);
#pragma unroll
        for (int q = 0; q < 8; q++) {
#pragma unroll
            for (int k = 0; k < 5; k++) {
                float wv = sw[og * 8 + q][c][k];
                unsigned long long wq = pk2(wv, wv);
                fma2(r01[q], pa[k], wq);
                fma2(r23[q], pa[k + 2], wq);
            }
        }
    }
    int p0 = P0 + 2 * tidp;
    long node0 = (long)b * RR + p0;
    float out0[8], out1[8];
#pragma unroll
    for (int q = 0; q < 8; q++) {
        float2 f01 = upk2(r01[q]), f23 = upk2(r23[q]);
        out0[q] = fmaxf(fmaxf(f01.x, f01.y), 0.f);
        out1[q] = fmaxf(fmaxf(f23.x, f23.y), 0.f);
    }
    float4* d0 = (float4*)&g_nodes[node0 * 32 + og * 8];
    float4* d1 = (float4*)&g_nodes[(node0 + 1) * 32 + og * 8];
    d0[0] = make_float4(out0[0], out0[1], out0[2], out0[3]);
    d0[1] = make_float4(out0[4], out0[5], out0[6], out0[7]);
    d1[0] = make_float4(out1[0], out1[1], out1[2], out1[3]);
    d1[1] = make_float4(out1[4], out1[5], out1[6], out1[7]);
}

// ---------------- agg smem layout: data[RR*32] | edges[NEDGE] | ptr[RR+1] ----
#define AGG_SMEM_BYTES (RR * 32 * 4 + NEDGE * 8 + (RR + 1) * 4)

// ---------------- agg32: 1024 thr, unroll-4, pre-scaled src ------------------
__global__ void k_agg32() {
    extern __shared__ char smemraw[];
    float* sx  = (float*)smemraw;
    int2*  se  = (int2*)(smemraw + RR * 32 * 4);
    int*  sptr = (int*)(smemraw + RR * 32 * 4 + NEDGE * 8);
    int b = blockIdx.x;
    int tid = threadIdx.x;
    const float4* inb = (const float4*)(g_nodes + (long)b * RR * 32);
    for (int id = tid; id < RR * 8; id += 1024)
        ((float4*)sx)[id] = inb[id];
    for (int id = tid; id < NEDGE; id += 1024)
        se[id] = g_edge[id];
    for (int id = tid; id <= RR; id += 1024)
        sptr[id] = g_ptr[id];
    __syncthreads();
    int warp = tid >> 5, lane = tid & 31;
    for (int t = warp; t < RR; t += 32) {
        int beg = sptr[t], end = sptr[t + 1];
        float a0 = 0.f, a1 = 0.f, a2 = 0.f, a3 = 0.f;
        int i = beg;
        for (; i + 3 < end; i += 4) {
            int2 e0 = se[i], e1 = se[i + 1], e2 = se[i + 2], e3 = se[i + 3];
            a0 = fmaf(__int_as_float(e0.y), sx[e0.x + lane], a0);
            a1 = fmaf(__int_as_float(e1.y), sx[e1.x + lane], a1);
            a2 = fmaf(__int_as_float(e2.y), sx[e2.x + lane], a2);
            a3 = fmaf(__int_as_float(e3.y), sx[e3.x + lane], a3);
        }
        for (; i < end; i++) {
            int2 e = se[i];
            a0 = fmaf(__int_as_float(e.y), sx[e.x + lane], a0);
        }
        g_xa[((long)b * RR + t) * 32 + lane] = (a0 + a1) + (a2 + a3);
    }
}

// ---------------- agg128: (quarter, sample), 1024 thr, unroll-4 --------------
__global__ void k_agg128() {
    extern __shared__ char smemraw[];
    float* sx  = (float*)smemraw;
    int2*  se  = (int2*)(smemraw + RR * 32 * 4);
    int*  sptr = (int*)(smemraw + RR * 32 * 4 + NEDGE * 8);
    int q = blockIdx.x;
    int b = blockIdx.y;
    int tid = threadIdx.x;
    const float* src_base = g_h1 + (long)b * RR * HID + q * 32;
    for (int id = tid; id < RR * 8; id += 1024) {
        int r = id >> 3, f4 = id & 7;
        ((float4*)sx)[id] = *(const float4*)(src_base + (long)r * HID + f4 * 4);
    }
    for (int id = tid; id < NEDGE; id += 1024)
        se[id] = g_edge[id];
    for (int id = tid; id <= RR; id += 1024)
        sptr[id] = g_ptr[id];
    __syncthreads();
    int warp = tid >> 5, lane = tid & 31;
    for (int t = warp; t < RR; t += 32) {
        int beg = sptr[t], end = sptr[t + 1];
        float a0 = 0.f, a1 = 0.f, a2 = 0.f, a3 = 0.f;
        int i = beg;
        for (; i + 3 < end; i += 4) {
            int2 e0 = se[i], e1 = se[i + 1], e2 = se[i + 2], e3 = se[i + 3];
            a0 = fmaf(__int_as_float(e0.y), sx[e0.x + lane], a0);
            a1 = fmaf(__int_as_float(e1.y), sx[e1.x + lane], a1);
            a2 = fmaf(__int_as_float(e2.y), sx[e2.x + lane], a2);
            a3 = fmaf(__int_as_float(e3.y), sx[e3.x + lane], a3);
        }
        for (; i < end; i++) {
            int2 e = se[i];
            a0 = fmaf(__int_as_float(e.y), sx[e.x + lane], a0);
        }
        g_h1a[((long)b * RR + t) * HID + q * 32 + lane] = (a0 + a1) + (a2 + a3);
    }
}

// ---- permuted W staging: ws2[k][m*16+cc] = (W[k][cc+32m], W[k][cc+16+32m]) --
__device__ __forceinline__ void stage_w_perm(float2 (*ws2)[64],
                                             const float* __restrict__ Wrow0,
                                             int tid, int nthr) {
    for (int id = tid; id < 1024; id += nthr) {
        int kk = id >> 5, c4 = id & 31;
        float4 v = *(const float4*)(Wrow0 + kk * HID + c4 * 4);
        int cbase = c4 * 4;
        float vv[4] = {v.x, v.y, v.z, v.w};
#pragma unroll
        for (int e = 0; e < 4; e++) {
            int c = cbase + e;
            int m = c >> 5, h = (c >> 4) & 1, cc = c & 15;
            ((float*)&ws2[kk][m * 16 + cc])[h] = vv[e];
        }
    }
}

// ---------------- GEMM1: [N,32]@[32,128] + bias, relu, FFMA2 -----------------
__global__ void k_gemm1(const float* __restrict__ W, const float* __restrict__ bias) {
    __shared__ float as[128][33];
    __shared__ float2 ws2[32][64];
    int tid = threadIdx.x;
    long rowBase = (long)blockIdx.x * 128;
    for (int id = tid; id < 1024; id += 256) {
        int r = id >> 3, k4 = id & 7;
        float4 v = *(const float4*)(g_xa + (rowBase + r) * 32 + k4 * 4);
        as[r][k4 * 4 + 0] = v.x; as[r][k4 * 4 + 1] = v.y;
        as[r][k4 * 4 + 2] = v.z; as[r][k4 * 4 + 3] = v.w;
    }
    stage_w_perm(ws2, W, tid, 256);
    __syncthreads();
    int rg = tid >> 4, cg = tid & 15, row0 = rg * 8;
    unsigned long long acc2[8][4];
#pragma unroll
    for (int i = 0; i < 8; i++)
#pragma unroll
        for (int m = 0; m < 4; m++) acc2[i][m] = 0ULL;
#pragma unroll
    for (int k = 0; k < 32; k++) {
        unsigned long long ap[8], bp[4];
#pragma unroll
        for (int i = 0; i < 8; i++) {
            float a = as[row0 + i][k];
            ap[i] = pk2(a, a);
        }
#pragma unroll
        for (int m = 0; m < 4; m++)
            bp[m] = *(const unsigned long long*)&ws2[k][m * 16 + cg];
#pragma unroll
        for (int i = 0; i < 8; i++)
#pragma unroll
            for (int m = 0; m < 4; m++) fma2(acc2[i][m], ap[i], bp[m]);
    }
#pragma unroll
    for (int i = 0; i < 8; i++)
#pragma unroll
        for (int m = 0; m < 4; m++) {
            float2 f = upk2(acc2[i][m]);
            int c0 = cg + 32 * m, c1 = cg + 16 + 32 * m;
            g_h1[(rowBase + row0 + i) * HID + c0] = fmaxf(f.x + bias[c0], 0.f);
            g_h1[(rowBase + row0 + i) * HID + c1] = fmaxf(f.y + bias[c1], 0.f);
        }
}

// ---------------- GEMM2 + bias + relu + mean, FFMA2 --------------------------
__global__ void k_gemm2m(const float* __restrict__ W, const float* __restrict__ bias) {
    __shared__ float as[128][33];
    __shared__ float2 ws2[32][64];
    __shared__ float smean[HID];
    int tid = threadIdx.x;
    long rowBase = (long)blockIdx.x * 128;
    int b = blockIdx.x >> 2;
    int rg = tid >> 4, cg = tid & 15, row0 = rg * 8;
    unsigned long long acc2[8][4];
#pragma unroll
    for (int i = 0; i < 8; i++)
#pragma unroll
        for (int m = 0; m < 4; m++) acc2[i][m] = 0ULL;
    for (int kc = 0; kc < 4; kc++) {
        __syncthreads();
        for (int id = tid; id < 1024; id += 256) {
            int r = id >> 3, k4 = id & 7;
            float4 v = *(const float4*)(g_h1a + (rowBase + r) * HID + kc * 32 + k4 * 4);
            as[r][k4 * 4 + 0] = v.x; as[r][k4 * 4 + 1] = v.y;
            as[r][k4 * 4 + 2] = v.z; as[r][k4 * 4 + 3] = v.w;
        }
        stage_w_perm(ws2, W + kc * 32 * HID, tid, 256);
        __syncthreads();
#pragma unroll
        for (int k = 0; k < 32; k++) {
            unsigned long long ap[8], bp[4];
#pragma unroll
            for (int i = 0; i < 8; i++) {
                float a = as[row0 + i][k];
                ap[i] = pk2(a, a);
            }
#pragma unroll
            for (int m = 0; m < 4; m++)
                bp[m] = *(const unsigned long long*)&ws2[k][m * 16 + cg];
#pragma unroll
            for (int i = 0; i < 8; i++)
#pragma unroll
                for (int m = 0; m < 4; m++) fma2(acc2[i][m], ap[i], bp[m]);
        }
    }
    if (tid < HID) smean[tid] = 0.f;
    __syncthreads();
#pragma unroll
    for (int m = 0; m < 4; m++) {
        int c0 = cg + 32 * m, c1 = cg + 16 + 32 * m;
        float b0 = bias[c0], b1 = bias[c1];
        float s0 = 0.f, s1 = 0.f;
#pragma unroll
        for (int i = 0; i < 8; i++) {
            float2 f = upk2(acc2[i][m]);
            s0 += fmaxf(f.x + b0, 0.f);
            s1 += fmaxf(f.y + b1, 0.f);
        }
        atomicAdd(&smean[c0], s0);
        atomicAdd(&smean[c1], s1);
    }
    __syncthreads();
    if (tid < HID) atomicAdd(&g_meanv[b * HID + tid], smean[tid] * (1.0f / RR));
}

// ---------------- fc ---------------------------------------------------------
__global__ void k_fc(const float* __restrict__ fw, const float* __restrict__ fb,
                     float* __restrict__ out) {
    int b = blockIdx.x;
    __shared__ float m[HID];
    m[threadIdx.x] = g_meanv[b * HID + threadIdx.x];
    __syncthreads();
    if (threadIdx.x < OUTF) {
        float acc = fb[threadIdx.x];
#pragma unroll
        for (int f = 0; f < HID; f++)
            acc = fmaf(m[f], fw[f * OUTF + threadIdx.x], acc);
        out[b * OUTF + threadIdx.x] = acc;
    }
}

// ---------------- launch ------------------------------------------------------
extern "C" void kernel_launch(void* const* d_in, const int* in_sizes, int n_in,
                              void* d_out, int out_size) {
    const float* x   = (const float*)d_in[0];
    const int*   ei  = (const int*)  d_in[1];
    const float* c1w = (const float*)d_in[2];
    const float* c1b = (const float*)d_in[3];
    const float* c2w = (const float*)d_in[4];
    const float* c2b = (const float*)d_in[5];
    const float* g1w = (const float*)d_in[6];
    const float* g1b = (const float*)d_in[7];
    const float* g2w = (const float*)d_in[8];
    const float* g2b = (const float*)d_in[9];
    const float* fw  = (const float*)d_in[10];
    const float* fb  = (const float*)d_in[11];
    float* out = (float*)d_out;
    int etot = in_sizes[1] / 2;

    static int attr_done = 0;
    if (!attr_done) {
        cudaFuncSetAttribute(k_agg32,  cudaFuncAttributeMaxDynamicSharedMemorySize, AGG_SMEM_BYTES);
        cudaFuncSetAttribute(k_agg128, cudaFuncAttributeMaxDynamicSharedMemorySize, AGG_SMEM_BYTES);
        attr_done = 1;
    }

    k_zero<<<1, RR>>>();
    k_count<<<ESING / 256, 256>>>(ei, etot);
    k_scan<<<1, RR>>>();
    k_fill<<<ESING / 256, 256>>>(ei, etot);
    k_conv1<<<dim3(T1 / 256, BATCH), 256>>>(x, c1w, c1b);
    k_conv2<<<dim3(RR / 256, BATCH), 512>>>(c2w, c2b);
    k_agg32<<<BATCH, 1024, AGG_SMEM_BYTES>>>();
    k_gemm1<<<NNODES / 128, 256>>>(g1w, g1b);
    k_agg128<<<dim3(4, BATCH), 1024, AGG_SMEM_BYTES>>>();
    k_gemm2m<<<NNODES / 128, 256>>>(g2w, g2b);
    k_fc<<<BATCH, HID>>>(fw, fb, out);
}